// round 16
// baseline (speedup 1.0000x reference)
#include <cuda_runtime.h>
#include <cstdint>

// RoIPooling (TF2 crop_and_resize bilinear, POOL=7)
// feature_map: (1, 256, 256, 512) float32 NHWC
// proposals:   (512, 4) int32  [x, y, w, h]
// output:      (512, 7, 7, 512) float32
//
// R12: = R11 (cp.async.cg depth-4 pipeline + CTA-uniform x/y elision,
// 20.96us, riding the chip LTS byte cap) + CTA-uniform SMALL-BOX fast path:
// for bw<=8 the unique x-corner columns form a contiguous range of
// ncols<=8; stage that range ONCE (unconditional loop, closed-form slot
// = ix - xbase, thread-private round trip, no barrier) instead of up to
// 14 duplicated column loads, then blend all 7 cells from smem.
// w=1 boxes drop from 7x duplicate loads to 1. Generic path untouched.

#define POOL 7
#define FM_W 256
#define FM_C 512
#define NPROP 512
#define C4 (FM_C / 4)
#define DEPTH 4
#define SB_NCOLS 8        // small-box max unique columns (bw<=8 guarantees this)

__device__ __forceinline__ void cp16(uint32_t dst_smem, const void* src) {
    asm volatile("cp.async.cg.shared.global [%0], [%1], 16;\n"
                 :: "r"(dst_smem), "l"(src) : "memory");
}
__device__ __forceinline__ void cp_commit() {
    asm volatile("cp.async.commit_group;\n" ::: "memory");
}
template <int N>
__device__ __forceinline__ void cp_wait() {
    asm volatile("cp.async.wait_group %0;\n" :: "n"(N) : "memory");
}

struct Ctx {
    const float4* row0;
    const float4* row1;
    float4*       orow;
    float wf, xscale, fy, ofy;
    int   bw, c;
    int   jb, jg, jd;  // generic-path consumer slot indices (loop-invariant)
    bool  need_y1;     // row1 contributes distinct bytes
    bool  need_x1;     // some px needs the x1 column
    uint32_t sbase;    // smem base address (bytes)
};

// x coords for cell px (bit-identical to reference float32 math)
__device__ __forceinline__ void xcoords(const Ctx& k, int px,
                                        int& ix0, int& ix1, float& fx) {
    float sx = ((float)px + 0.5f) * k.xscale - 0.5f;
    sx = fminf(fmaxf(sx, 0.0f), k.wf - 1.0f);
    ix0 = (int)floorf(sx);
    ix1 = min(ix0 + 1, k.bw - 1);
    fx  = sx - (float)ix0;
}

// generic stage slot: slot s, corner j, thread t
__device__ __forceinline__ uint32_t slot_addr(const Ctx& k, int s, int j) {
    return k.sbase + (uint32_t)(((s * 4 + j) * 128 + k.c) * 16);
}

__device__ __forceinline__ void issue(const Ctx& k, int px) {
    int ix0, ix1; float fx;
    xcoords(k, px, ix0, ix1, fx);
    const int s = px & (DEPTH - 1);
    cp16(slot_addr(k, s, 0), &k.row0[ix0 * C4 + k.c]);
    if (k.need_x1)                cp16(slot_addr(k, s, 1), &k.row0[ix1 * C4 + k.c]);
    if (k.need_y1)                cp16(slot_addr(k, s, 2), &k.row1[ix0 * C4 + k.c]);
    if (k.need_x1 && k.need_y1)   cp16(slot_addr(k, s, 3), &k.row1[ix1 * C4 + k.c]);
    cp_commit();
}

template <int WC>
__device__ __forceinline__ void consume(const Ctx& k, const float4* buf, int px) {
    int ix0, ix1; float fx;
    xcoords(k, px, ix0, ix1, fx);
    const float of = 1.0f - fx;
    const int s = px & (DEPTH - 1);

    cp_wait<WC>();

    const float4 a = buf[(s * 4 + 0)    * 128 + k.c];
    const float4 b = buf[(s * 4 + k.jb) * 128 + k.c];
    const float4 g = buf[(s * 4 + k.jg) * 128 + k.c];
    const float4 d = buf[(s * 4 + k.jd) * 128 + k.c];

    float4 o;
    o.x = (a.x * of + b.x * fx) * k.ofy + (g.x * of + d.x * fx) * k.fy;
    o.y = (a.y * of + b.y * fx) * k.ofy + (g.y * of + d.y * fx) * k.fy;
    o.z = (a.z * of + b.z * fx) * k.ofy + (g.z * of + d.z * fx) * k.fy;
    o.w = (a.w * of + b.w * fx) * k.ofy + (g.w * of + d.w * fx) * k.fy;

    __stcs(&k.orow[px * C4 + k.c], o);
}

// ---- small-box fast path (bw <= 8): unique columns are contiguous ----
// smem layout: slot (r*SB_NCOLS + off)*128 + c, r=0 row0, r=1 row1.
__device__ __forceinline__ void small_box_body(const Ctx& k, const float4* buf) {
    // unique column range [xbase, xbase+ncols)
    int t0, t1; float tf;
    xcoords(k, 0, t0, t1, tf);  const int xbase = t0;
    xcoords(k, 6, t0, t1, tf);  const int ncols = t1 - xbase + 1;   // <= 8

    // stage the range once (unconditional loop body; thread-private copies)
    for (int off = 0; off < ncols; ++off) {
        const int ix = xbase + off;
        cp16(k.sbase + (uint32_t)(((0 * SB_NCOLS + off) * 128 + k.c) * 16),
             &k.row0[ix * C4 + k.c]);
        if (k.need_y1)
            cp16(k.sbase + (uint32_t)(((1 * SB_NCOLS + off) * 128 + k.c) * 16),
                 &k.row1[ix * C4 + k.c]);
    }
    cp_commit();
    cp_wait<0>();                       // thread-private round trip: no barrier

    const int yoff = k.need_y1 ? SB_NCOLS : 0;   // row1 base (loop-invariant)

    #pragma unroll
    for (int px = 0; px < POOL; ++px) {
        int ix0, ix1; float fx;
        xcoords(k, px, ix0, ix1, fx);
        const float of  = 1.0f - fx;
        const int   s0x = ix0 - xbase;
        const int   s1x = ix1 - xbase;

        const float4 a = buf[(s0x)        * 128 + k.c];
        const float4 b = buf[(s1x)        * 128 + k.c];
        const float4 g = buf[(yoff + s0x) * 128 + k.c];
        const float4 d = buf[(yoff + s1x) * 128 + k.c];

        float4 o;
        o.x = (a.x * of + b.x * fx) * k.ofy + (g.x * of + d.x * fx) * k.fy;
        o.y = (a.y * of + b.y * fx) * k.ofy + (g.y * of + d.y * fx) * k.fy;
        o.z = (a.z * of + b.z * fx) * k.ofy + (g.z * of + d.z * fx) * k.fy;
        o.w = (a.w * of + b.w * fx) * k.ofy + (g.w * of + d.w * fx) * k.fy;

        __stcs(&k.orow[px * C4 + k.c], o);
    }
}

__global__ __launch_bounds__(128)
void roi_pool_kernel(const float* __restrict__ fm,
                     const int*   __restrict__ props,
                     float*       __restrict__ out)
{
    __shared__ float4 buf[DEPTH * 4 * 128];    // 32 KB (both paths fit)

    const int bid = blockIdx.x;                // 0 .. 3583
    const int n   = bid / POOL;
    const int py  = bid - n * POOL;

    const int4 box = reinterpret_cast<const int4*>(props)[n];
    const int bx = box.x, by = box.y, bw = box.z, bh = box.w;

    // --- y axis coords ---
    const float hf = (float)bh;
    float sy = ((float)py + 0.5f) * (hf / (float)POOL) - 0.5f;
    sy = fminf(fmaxf(sy, 0.0f), hf - 1.0f);
    const int   iy0 = (int)floorf(sy);
    const int   iy1 = min(iy0 + 1, bh - 1);

    Ctx k;
    k.fy  = sy - (float)iy0;
    k.ofy = 1.0f - k.fy;
    k.need_y1 = (iy1 != iy0) && (k.fy != 0.0f);
    k.row0 = reinterpret_cast<const float4*>(fm + ((size_t)(by + iy0) * FM_W + bx) * FM_C);
    k.row1 = reinterpret_cast<const float4*>(fm + ((size_t)(by + iy1) * FM_W + bx) * FM_C);
    k.orow = reinterpret_cast<float4*>(out + ((size_t)n * (POOL * POOL) + (size_t)py * POOL) * FM_C);
    k.c   = threadIdx.x;
    k.bw  = bw;
    k.wf  = (float)bw;
    k.xscale = k.wf / (float)POOL;
    {
        uint32_t a;
        asm("{ .reg .u64 t; cvta.to.shared.u64 t, %1; cvt.u32.u64 %0, t; }"
            : "=r"(a) : "l"((const void*)buf));
        k.sbase = a;
    }

    // ---- CTA-uniform dispatch: small boxes take the dedup path ----
    if (bw <= 8) {
        small_box_body(k, buf);
        return;
    }

    // CTA-uniform x flag: does ANY px cell need the x1 column?
    {
        bool nx = false;
        #pragma unroll
        for (int px = 0; px < POOL; ++px) {
            int i0, i1; float fr;
            xcoords(k, px, i0, i1, fr);
            nx |= ((i1 != i0) && (fr != 0.0f));
        }
        k.need_x1 = nx;
    }
    k.jb = k.need_x1 ? 1 : 0;
    k.jg = k.need_y1 ? 2 : 0;
    k.jd = k.need_y1 ? (k.need_x1 ? 3 : 2) : k.jb;

    // prologue: fill the pipe (4 stages in flight)
    issue(k, 0); issue(k, 1); issue(k, 2); issue(k, 3);

    // steady state + drain
    consume<3>(k, buf, 0); issue(k, 4);
    consume<3>(k, buf, 1); issue(k, 5);
    consume<3>(k, buf, 2); issue(k, 6);
    consume<3>(k, buf, 3);
    consume<2>(k, buf, 4);
    consume<1>(k, buf, 5);
    consume<0>(k, buf, 6);
}

extern "C" void kernel_launch(void* const* d_in, const int* in_sizes, int n_in,
                              void* d_out, int out_size)
{
    const float* fm    = (const float*)d_in[0];
    const int*   props = (const int*)d_in[1];
    float*       out   = (float*)d_out;

    const int blocks = NPROP * POOL;      // 3584
    roi_pool_kernel<<<blocks, 128>>>(fm, props, out);
}

// round 17
// speedup vs baseline: 1.0287x; 1.0287x over previous
#include <cuda_runtime.h>
#include <cstdint>

// RoIPooling (TF2 crop_and_resize bilinear, POOL=7)
// feature_map: (1, 256, 256, 512) float32 NHWC
// proposals:   (512, 4) int32  [x, y, w, h]
// output:      (512, 7, 7, 512) float32
//
// R13: = R11 (cp.async.cg depth-4 pipeline + CTA-uniform x/y corner
// elision; ~240MB L2 traffic) with the pipeline body FULLY TEMPLATED on
// <NEED_X1, NEED_Y1>. R11 ran its bytes at only 11.2TB/s vs R6's 11.9TB/s
// because runtime flags/slot-indices polluted the hot loop; one dispatch
// into 4 branchless instantiations makes the dominant <true,true> body
// SASS-identical to R6 while keeping the byte cuts. (R12's small-box path
// reverted: regs 79 for all CTAs, net loss.)

#define POOL 7
#define FM_W 256
#define FM_C 512
#define NPROP 512
#define C4 (FM_C / 4)
#define DEPTH 4

__device__ __forceinline__ void cp16(uint32_t dst_smem, const void* src) {
    asm volatile("cp.async.cg.shared.global [%0], [%1], 16;\n"
                 :: "r"(dst_smem), "l"(src) : "memory");
}
__device__ __forceinline__ void cp_commit() {
    asm volatile("cp.async.commit_group;\n" ::: "memory");
}
template <int N>
__device__ __forceinline__ void cp_wait() {
    asm volatile("cp.async.wait_group %0;\n" :: "n"(N) : "memory");
}

struct Ctx {
    const float4* row0;
    const float4* row1;
    float4*       orow;
    float wf, xscale, fy, ofy;
    int   bw, c;
    uint32_t sbase;   // smem base address (bytes)
};

// x coords for cell px (bit-identical to reference float32 math)
__device__ __forceinline__ void xcoords(const Ctx& k, int px,
                                        int& ix0, int& ix1, float& fx) {
    float sx = ((float)px + 0.5f) * k.xscale - 0.5f;
    sx = fminf(fmaxf(sx, 0.0f), k.wf - 1.0f);
    ix0 = (int)floorf(sx);
    ix1 = min(ix0 + 1, k.bw - 1);
    fx  = sx - (float)ix0;
}

// stage slot layout: slot s, corner j, thread t at sbase + ((s*4+j)*128 + t)*16
__device__ __forceinline__ uint32_t slot_addr(const Ctx& k, int s, int j) {
    return k.sbase + (uint32_t)(((s * 4 + j) * 128 + k.c) * 16);
}

template <bool NX, bool NY>
__device__ __forceinline__ void issue(const Ctx& k, int px) {
    int ix0, ix1; float fx;
    xcoords(k, px, ix0, ix1, fx);
    const int s = px & (DEPTH - 1);
    cp16(slot_addr(k, s, 0), &k.row0[ix0 * C4 + k.c]);
    if (NX)       cp16(slot_addr(k, s, 1), &k.row0[ix1 * C4 + k.c]);
    if (NY)       cp16(slot_addr(k, s, 2), &k.row1[ix0 * C4 + k.c]);
    if (NX && NY) cp16(slot_addr(k, s, 3), &k.row1[ix1 * C4 + k.c]);
    cp_commit();
}

template <bool NX, bool NY, int WC>
__device__ __forceinline__ void consume(const Ctx& k, const float4* buf, int px) {
    // compile-time slot remap: elided corners alias the staged duplicate
    // (bit-exact: same pixel, or weight exactly 0.0)
    constexpr int JB = NX ? 1 : 0;
    constexpr int JG = NY ? 2 : 0;
    constexpr int JD = NY ? (NX ? 3 : 2) : JB;

    int ix0, ix1; float fx;
    xcoords(k, px, ix0, ix1, fx);          // recompute (cheap ALU, saves regs)
    const float of = 1.0f - fx;
    const int s = px & (DEPTH - 1);

    cp_wait<WC>();                          // stage px's group retired

    const float4 a = buf[(s * 4 + 0)  * 128 + k.c];
    const float4 b = buf[(s * 4 + JB) * 128 + k.c];
    const float4 g = buf[(s * 4 + JG) * 128 + k.c];
    const float4 d = buf[(s * 4 + JD) * 128 + k.c];

    float4 o;
    o.x = (a.x * of + b.x * fx) * k.ofy + (g.x * of + d.x * fx) * k.fy;
    o.y = (a.y * of + b.y * fx) * k.ofy + (g.y * of + d.y * fx) * k.fy;
    o.z = (a.z * of + b.z * fx) * k.ofy + (g.z * of + d.z * fx) * k.fy;
    o.w = (a.w * of + b.w * fx) * k.ofy + (g.w * of + d.w * fx) * k.fy;

    __stcs(&k.orow[px * C4 + k.c], o);
}

template <bool NX, bool NY>
__device__ __forceinline__ void run(const Ctx& k, const float4* buf) {
    // prologue: fill the pipe (4 stages in flight)
    issue<NX, NY>(k, 0); issue<NX, NY>(k, 1);
    issue<NX, NY>(k, 2); issue<NX, NY>(k, 3);

    // steady state + drain; wait counts keep exactly stage-px retired
    consume<NX, NY, 3>(k, buf, 0); issue<NX, NY>(k, 4);
    consume<NX, NY, 3>(k, buf, 1); issue<NX, NY>(k, 5);
    consume<NX, NY, 3>(k, buf, 2); issue<NX, NY>(k, 6);
    consume<NX, NY, 3>(k, buf, 3);
    consume<NX, NY, 2>(k, buf, 4);
    consume<NX, NY, 1>(k, buf, 5);
    consume<NX, NY, 0>(k, buf, 6);
}

__global__ __launch_bounds__(128)
void roi_pool_kernel(const float* __restrict__ fm,
                     const int*   __restrict__ props,
                     float*       __restrict__ out)
{
    __shared__ float4 buf[DEPTH * 4 * 128];    // 32 KB

    const int bid = blockIdx.x;                // 0 .. 3583
    const int n   = bid / POOL;
    const int py  = bid - n * POOL;

    const int4 box = reinterpret_cast<const int4*>(props)[n];
    const int bx = box.x, by = box.y, bw = box.z, bh = box.w;

    // --- y axis coords ---
    const float hf = (float)bh;
    float sy = ((float)py + 0.5f) * (hf / (float)POOL) - 0.5f;
    sy = fminf(fmaxf(sy, 0.0f), hf - 1.0f);
    const int   iy0 = (int)floorf(sy);
    const int   iy1 = min(iy0 + 1, bh - 1);

    Ctx k;
    k.fy  = sy - (float)iy0;
    k.ofy = 1.0f - k.fy;
    k.row0 = reinterpret_cast<const float4*>(fm + ((size_t)(by + iy0) * FM_W + bx) * FM_C);
    k.row1 = reinterpret_cast<const float4*>(fm + ((size_t)(by + iy1) * FM_W + bx) * FM_C);
    k.orow = reinterpret_cast<float4*>(out + ((size_t)n * (POOL * POOL) + (size_t)py * POOL) * FM_C);
    k.c   = threadIdx.x;
    k.bw  = bw;
    k.wf  = (float)bw;
    k.xscale = k.wf / (float)POOL;
    {
        uint32_t a;
        asm("{ .reg .u64 t; cvta.to.shared.u64 t, %1; cvt.u32.u64 %0, t; }"
            : "=r"(a) : "l"((const void*)buf));
        k.sbase = a;
    }

    const bool need_y1 = (iy1 != iy0) && (k.fy != 0.0f);

    // CTA-uniform x flag: does ANY px cell need the x1 column?
    bool need_x1 = false;
    #pragma unroll
    for (int px = 0; px < POOL; ++px) {
        int i0, i1; float fr;
        xcoords(k, px, i0, i1, fr);
        need_x1 |= ((i1 != i0) && (fr != 0.0f));
    }

    // single CTA-uniform dispatch into branchless specialized bodies
    if (need_x1) {
        if (need_y1) run<true,  true >(k, buf);
        else         run<true,  false>(k, buf);
    } else {
        if (need_y1) run<false, true >(k, buf);
        else         run<false, false>(k, buf);
    }
}

extern "C" void kernel_launch(void* const* d_in, const int* in_sizes, int n_in,
                              void* d_out, int out_size)
{
    const float* fm    = (const float*)d_in[0];
    const int*   props = (const int*)d_in[1];
    float*       out   = (float*)d_out;

    const int blocks = NPROP * POOL;      // 3584
    roi_pool_kernel<<<blocks, 128>>>(fm, props, out);
}